// round 15
// baseline (speedup 1.0000x reference)
#include <cuda_runtime.h>
#include <cuda_fp16.h>
#include <cstdint>

#define NB   4
#define SEQ  2048
#define EDIM 1024
#define H3   3072
#define NH   16
#define NTOK (NB*SEQ)

// Q pre-scale: (1/sqrt(64)) * log2(e)  -> scores land in log2 domain
#define QSCALE 0.180336880111120432f

// Scratch (device globals: allocation-free, graph-capture safe)
__device__ __half g_QKV[(size_t)NTOK * H3];    // [token][Qall(scaled)|Kall|Vall]
__device__ __half g_ATT[(size_t)NTOK * EDIM];  // attention out
__device__ __half g_X  [(size_t)NTOK * EDIM];  // x in half
__device__ __half g_W1T[(size_t)H3   * EDIM];  // W1^T, rows permuted [Q|K|V]
__device__ __half g_W2T[(size_t)EDIM * EDIM];  // W2^T

__device__ __forceinline__ void mma_f16(float d[4],
                                        uint32_t a0, uint32_t a1, uint32_t a2, uint32_t a3,
                                        uint32_t b0, uint32_t b1) {
    asm volatile(
        "mma.sync.aligned.m16n8k16.row.col.f32.f16.f16.f32 "
        "{%0,%1,%2,%3}, {%4,%5,%6,%7}, {%8,%9}, {%0,%1,%2,%3};"
        : "+f"(d[0]), "+f"(d[1]), "+f"(d[2]), "+f"(d[3])
        : "r"(a0), "r"(a1), "r"(a2), "r"(a3), "r"(b0), "r"(b1));
}
__device__ __forceinline__ uint32_t smaddr(const void* p) {
    return (uint32_t)__cvta_generic_to_shared(p);
}
__device__ __forceinline__ void ldsm_x4(uint32_t r[4], uint32_t addr) {
    asm volatile("ldmatrix.sync.aligned.m8n8.x4.shared.b16 {%0,%1,%2,%3}, [%4];"
                 : "=r"(r[0]), "=r"(r[1]), "=r"(r[2]), "=r"(r[3]) : "r"(addr));
}
__device__ __forceinline__ void ldsm_x4_t(uint32_t r[4], uint32_t addr) {
    asm volatile("ldmatrix.sync.aligned.m8n8.x4.trans.shared.b16 {%0,%1,%2,%3}, [%4];"
                 : "=r"(r[0]), "=r"(r[1]), "=r"(r[2]), "=r"(r[3]) : "r"(addr));
}
__device__ __forceinline__ void cp16(uint32_t dst, const void* src) {
    asm volatile("cp.async.cg.shared.global [%0], [%1], 16;\n" :: "r"(dst), "l"(src));
}
#define CP_COMMIT()  asm volatile("cp.async.commit_group;\n" ::: "memory")
#define CP_WAIT(n)   asm volatile("cp.async.wait_group %0;\n" :: "n"(n) : "memory")

__device__ __forceinline__ float ex2(float x) {
    float y;
    asm("ex2.approx.ftz.f32 %0, %1;" : "=f"(y) : "f"(x));
    return y;
}
// packed: returns half2 { lo = 2^lo_in, hi = 2^hi_in }
__device__ __forceinline__ uint32_t ex2_h2(float lo, float hi) {
    uint32_t c, r;
    asm("cvt.rn.f16x2.f32 %0, %1, %2;" : "=r"(c) : "f"(hi), "f"(lo));
    asm("ex2.approx.f16x2 %0, %1;" : "=r"(r) : "r"(c));
    return r;
}
__device__ __forceinline__ uint32_t h2u(__half2 h) {
    union { __half2 h; uint32_t u; } c; c.h = h; return c.u;
}

// ---------------------------------------------------------------------------
// Merged pre-pass: block ranges dispatch x-convert / W1 trans / W2 trans.
// ---------------------------------------------------------------------------
#define XB   (NTOK * EDIM / 4 / 256)        // 8192
#define W1B  ((H3 / 32) * (EDIM / 32))      // 3072
#define W2B  ((EDIM / 32) * (EDIM / 32))    // 1024

__global__ __launch_bounds__(256)
void prepass(const float* __restrict__ x, const float* __restrict__ W1,
             const float* __restrict__ W2, __half* __restrict__ Xh,
             __half* __restrict__ W1T, __half* __restrict__ W2T)
{
    __shared__ float t[32][33];
    int bid = blockIdx.x;
    if (bid < XB) {
        int i = bid * 256 + threadIdx.x;
        float4 v = ((const float4*)x)[i];
        uint2 o;
        o.x = h2u(__floats2half2_rn(v.x, v.y));
        o.y = h2u(__floats2half2_rn(v.z, v.w));
        ((uint2*)Xh)[i] = o;
        return;
    }
    const float* W;
    __half* WT;
    int NC, K = EDIM;
    bool perm;
    int idx;
    if (bid < XB + W1B) {
        idx = bid - XB; W = W1; WT = W1T; NC = H3; perm = true;
    } else {
        idx = bid - XB - W1B; W = W2; WT = W2T; NC = EDIM; perm = false;
    }
    int nbx = NC / 32;
    int bx = idx % nbx, by = idx / nbx;
    int tx = threadIdx.x & 31, ty = threadIdx.x >> 5;
    int c0 = bx * 32, k0 = by * 32;
    #pragma unroll
    for (int i = 0; i < 32; i += 8)
        t[ty + i][tx] = W[(size_t)(k0 + ty + i) * NC + c0 + tx];
    __syncthreads();
    int cbase = perm ? ((c0 % 192) / 64) * 1024 + (c0 / 192) * 64 + (c0 % 64) : c0;
    #pragma unroll
    for (int i = 0; i < 32; i += 8) {
        int j = ty + i;
        WT[(size_t)(cbase + j) * K + k0 + tx] = __float2half_rn(t[tx][j]);
    }
}

// ---------------------------------------------------------------------------
// FP16 GEMM (same as R14): C = A @ Bt^T + bias. A/C pointers pre-offset per
// batch chunk; grid.y covers the chunk's M tiles.
// ---------------------------------------------------------------------------
template<int MODE>
__global__ __launch_bounds__(128, 2)
void gemm_f16(const __half* __restrict__ A, const __half* __restrict__ Bt,
              const float* __restrict__ bias, void* __restrict__ Cout,
              int M, int Nstride, int K)
{
    extern __shared__ __half sh[];
    __half (*As)[128][72] = (__half (*)[128][72])sh;                 // 3 stages
    __half (*Bs)[128][72] = (__half (*)[128][72])(sh + 3 * 128 * 72);

    const int tid  = threadIdx.x;
    const int bm   = blockIdx.y, bn = blockIdx.x;
    const int warp = tid >> 5, lane = tid & 31;
    const int wm   = (warp >> 1) * 64;
    const int wn   = (warp & 1) * 64;
    const int lr   = lane >> 2, lc = lane & 3;

    const int arow = wm + ((lane >> 3) & 1) * 8 + (lane & 7);
    const int ach  = ((lane >> 4) & 1) * 8;
    const int brow = wn + ((lane >> 4) & 1) * 8 + (lane & 7);
    const int bch  = ((lane >> 3) & 1) * 8;

    const int ntiles = K >> 6;

    float d[4][8][4];
    #pragma unroll
    for (int mt = 0; mt < 4; mt++)
        #pragma unroll
        for (int nt = 0; nt < 8; nt++)
            #pragma unroll
            for (int r = 0; r < 4; r++) d[mt][nt][r] = 0.f;

    auto prefetch = [&](int t, int buf) {
        int k0 = t << 6;
        #pragma unroll
        for (int i = 0; i < 8; i++) {
            int idx = i * 128 + tid;
            int r = idx >> 3, c = idx & 7;
            cp16(smaddr(&As[buf][r][c * 8]), A  + (size_t)(bm * 128 + r) * K + k0 + c * 8);
        }
        #pragma unroll
        for (int i = 0; i < 8; i++) {
            int idx = i * 128 + tid;
            int r = idx >> 3, c = idx & 7;
            cp16(smaddr(&Bs[buf][r][c * 8]), Bt + (size_t)(bn * 128 + r) * K + k0 + c * 8);
        }
        CP_COMMIT();
    };

    auto load_frags = [&](int cur, int kt, uint32_t (&a)[4][4], uint32_t (&b)[8][2]) {
        #pragma unroll
        for (int mt = 0; mt < 4; mt++)
            ldsm_x4(a[mt], smaddr(&As[cur][arow + mt * 16][kt * 16 + ach]));
        #pragma unroll
        for (int ntp = 0; ntp < 4; ntp++) {
            uint32_t t4[4];
            ldsm_x4(t4, smaddr(&Bs[cur][brow + ntp * 16][kt * 16 + bch]));
            b[2 * ntp][0] = t4[0]; b[2 * ntp][1] = t4[1];
            b[2 * ntp + 1][0] = t4[2]; b[2 * ntp + 1][1] = t4[3];
        }
    };

    prefetch(0, 0);
    prefetch(1, 1);

    for (int t = 0; t < ntiles; t++) {
        int cur = t % 3;
        if (t + 1 < ntiles) { CP_WAIT(1); } else { CP_WAIT(0); }
        __syncthreads();
        if (t + 2 < ntiles) prefetch(t + 2, (t + 2) % 3);

        uint32_t a[2][4][4], b[2][8][2];
        load_frags(cur, 0, a[0], b[0]);
        #pragma unroll
        for (int kt = 0; kt < 4; kt++) {
            int cf = kt & 1;
            if (kt < 3) load_frags(cur, kt + 1, a[cf ^ 1], b[cf ^ 1]);
            #pragma unroll
            for (int mt = 0; mt < 4; mt++)
                #pragma unroll
                for (int nt = 0; nt < 8; nt++)
                    mma_f16(d[mt][nt], a[cf][mt][0], a[cf][mt][1],
                            a[cf][mt][2], a[cf][mt][3], b[cf][nt][0], b[cf][nt][1]);
        }
    }

    #pragma unroll
    for (int mt = 0; mt < 4; mt++) {
        #pragma unroll
        for (int nt = 0; nt < 8; nt++) {
            int row  = bm * 128 + wm + mt * 16 + lr;
            int colg = bn * 128 + wn + nt * 8 + 2 * lc;
            float2 bv;
            if (MODE == 1) {
                int map = ((colg & 1023) >> 6) * 192 + (colg >> 10) * 64 + (colg & 63);
                bv = *(const float2*)(bias + map);
            } else {
                bv = *(const float2*)(bias + colg);
            }
            float e0 = d[mt][nt][0] + bv.x, e1 = d[mt][nt][1] + bv.y;
            float e2 = d[mt][nt][2] + bv.x, e3 = d[mt][nt][3] + bv.y;
            if (MODE == 0) {
                float* C = (float*)Cout;
                *(float2*)(C + (size_t)row * Nstride + colg)       = make_float2(e0, e1);
                *(float2*)(C + (size_t)(row + 8) * Nstride + colg) = make_float2(e2, e3);
            } else {
                float s = (colg < 1024) ? QSCALE : 1.0f;
                __half* C = (__half*)Cout;
                *(__half2*)(C + (size_t)row * Nstride + colg) =
                    __floats2half2_rn(e0 * s, e1 * s);
                *(__half2*)(C + (size_t)(row + 8) * Nstride + colg) =
                    __floats2half2_rn(e2 * s, e3 * s);
            }
        }
    }
}

// ---------------------------------------------------------------------------
// Flash attention (same math as R14). Pointers pre-offset per batch; grid
// (SEQ/128, NH, 1), block 128.
// smem: Qs[128][72] | Ks[2][128][72] | Vs[2][128][72]  = 92160 B
// ---------------------------------------------------------------------------
__global__ __launch_bounds__(128, 2)
void attn_f16(const __half* __restrict__ Qkv, __half* __restrict__ Out)
{
    extern __shared__ __half smp[];
    __half* Qs = smp;                                          // [128][72]
    __half (*Ks)[128][72] = (__half (*)[128][72])(smp + 128 * 72);
    __half (*Vs)[128][72] = (__half (*)[128][72])(smp + 128 * 72 + 2 * 128 * 72);

    const int qb = blockIdx.x, h = blockIdx.y;
    const int tid = threadIdx.x, warp = tid >> 5, lane = tid & 31;
    const int lr = lane >> 2, lc = lane & 3;

    const __half* Qbase = Qkv + h * 64;
    const __half* Kbase = Qbase + 1024;
    const __half* Vbase = Qbase + 2048;

    const int ar  = warp * 32 + ((lane >> 3) & 1) * 8 + (lane & 7);
    const int ach = ((lane >> 4) & 1) * 8;
    const int br  = ((lane >> 4) & 1) * 8 + (lane & 7);
    const int bch = ((lane >> 3) & 1) * 8;
    const int vtr = ((lane >> 3) & 1) * 8 + (lane & 7);
    const int vtc = ((lane >> 4) & 1) * 8;

    const uint32_t lfrag = (lr == 0) ? 0x3C003C00u : 0u;

    auto prefetch_kv = [&](int t, int buf) {
        #pragma unroll
        for (int i = 0; i < 8; i++) {
            int idx = i * 128 + tid;
            int r = idx >> 3, c = idx & 7;
            cp16(smaddr(&Ks[buf][r][c * 8]),
                 Kbase + (size_t)(t * 128 + r) * H3 + c * 8);
            cp16(smaddr(&Vs[buf][r][c * 8]),
                 Vbase + (size_t)(t * 128 + r) * H3 + c * 8);
        }
        CP_COMMIT();
    };

    auto load_vfrags = [&](int cur, int j, int kt, uint32_t (&bb)[8][2]) {
        #pragma unroll
        for (int ntp = 0; ntp < 4; ntp++) {
            uint32_t t4[4];
            ldsm_x4_t(t4, smaddr(&Vs[cur][j * 64 + kt * 16 + vtr][ntp * 16 + vtc]));
            bb[2 * ntp][0] = t4[0]; bb[2 * ntp][1] = t4[1];
            bb[2 * ntp + 1][0] = t4[2]; bb[2 * ntp + 1][1] = t4[3];
        }
    };

    #pragma unroll
    for (int i = 0; i < 8; i++) {
        int idx = i * 128 + tid;
        int r = idx >> 3, c = idx & 7;
        cp16(smaddr(&Qs[r * 72 + c * 8]),
             Qbase + (size_t)(qb * 128 + r) * H3 + c * 8);
    }
    prefetch_kv(0, 0);

    CP_WAIT(0);
    __syncthreads();

    uint32_t aq[4][2][4];
    #pragma unroll
    for (int kt = 0; kt < 4; kt++)
        #pragma unroll
        for (int mi = 0; mi < 2; mi++)
            ldsm_x4(aq[kt][mi], smaddr(&Qs[(ar + mi * 16) * 72 + kt * 16 + ach]));

    float o[2][9][4];
    #pragma unroll
    for (int mi = 0; mi < 2; mi++)
        #pragma unroll
        for (int nt = 0; nt < 9; nt++)
            #pragma unroll
            for (int r = 0; r < 4; r++) o[mi][nt][r] = 0.f;
    float mm[2][2] = {{-1e30f, -1e30f}, {-1e30f, -1e30f}};

    const int NT = SEQ / 128;
    for (int t = 0; t < NT; t++) {
        int cur = t & 1;
        if (t > 0) {
            CP_WAIT(0);
            __syncthreads();
        }
        if (t + 1 < NT) prefetch_kv(t + 1, cur ^ 1);

        #pragma unroll
        for (int j = 0; j < 2; j++) {
            float s[2][8][4];
            #pragma unroll
            for (int mi = 0; mi < 2; mi++)
                #pragma unroll
                for (int nt = 0; nt < 8; nt++)
                    #pragma unroll
                    for (int r = 0; r < 4; r++) s[mi][nt][r] = 0.f;
            uint32_t kb[2][8][2];
            {
                uint32_t t4[4];
                #pragma unroll
                for (int ntp = 0; ntp < 4; ntp++) {
                    ldsm_x4(t4, smaddr(&Ks[cur][j * 64 + br + ntp * 16][bch]));
                    kb[0][2 * ntp][0] = t4[0]; kb[0][2 * ntp][1] = t4[1];
                    kb[0][2 * ntp + 1][0] = t4[2]; kb[0][2 * ntp + 1][1] = t4[3];
                }
            }
            #pragma unroll
            for (int kt = 0; kt < 4; kt++) {
                int cf = kt & 1;
                if (kt < 3) {
                    uint32_t t4[4];
                    #pragma unroll
                    for (int ntp = 0; ntp < 4; ntp++) {
                        ldsm_x4(t4, smaddr(&Ks[cur][j * 64 + br + ntp * 16]
                                                   [(kt + 1) * 16 + bch]));
                        kb[cf ^ 1][2 * ntp][0] = t4[0];
                        kb[cf ^ 1][2 * ntp][1] = t4[1];
                        kb[cf ^ 1][2 * ntp + 1][0] = t4[2];
                        kb[cf ^ 1][2 * ntp + 1][1] = t4[3];
                    }
                }
                #pragma unroll
                for (int mi = 0; mi < 2; mi++)
                    #pragma unroll
                    for (int nt = 0; nt < 8; nt++)
                        mma_f16(s[mi][nt], aq[kt][mi][0], aq[kt][mi][1],
                                aq[kt][mi][2], aq[kt][mi][3],
                                kb[cf][nt][0], kb[cf][nt][1]);
            }

            float al[2][2];
            #pragma unroll
            for (int mi = 0; mi < 2; mi++) {
                float mx0 = s[mi][0][0], mx1 = s[mi][0][2];
                #pragma unroll
                for (int nt = 0; nt < 8; nt++) {
                    mx0 = fmaxf(mx0, fmaxf(s[mi][nt][0], s[mi][nt][1]));
                    mx1 = fmaxf(mx1, fmaxf(s[mi][nt][2], s[mi][nt][3]));
                }
                mx0 = fmaxf(mx0, __shfl_xor_sync(0xffffffffu, mx0, 1));
                mx0 = fmaxf(mx0, __shfl_xor_sync(0xffffffffu, mx0, 2));
                mx1 = fmaxf(mx1, __shfl_xor_sync(0xffffffffu, mx1, 1));
                mx1 = fmaxf(mx1, __shfl_xor_sync(0xffffffffu, mx1, 2));
                float nm0 = fmaxf(mm[mi][0], mx0), nm1 = fmaxf(mm[mi][1], mx1);
                al[mi][0] = ex2(mm[mi][0] - nm0);
                al[mi][1] = ex2(mm[mi][1] - nm1);
                mm[mi][0] = nm0; mm[mi][1] = nm1;
            }
            if (!__all_sync(0xffffffffu,
                            (al[0][0] == 1.f) && (al[0][1] == 1.f) &&
                            (al[1][0] == 1.f) && (al[1][1] == 1.f))) {
                #pragma unroll
                for (int mi = 0; mi < 2; mi++)
                    #pragma unroll
                    for (int nt = 0; nt < 9; nt++) {
                        o[mi][nt][0] *= al[mi][0]; o[mi][nt][1] *= al[mi][0];
                        o[mi][nt][2] *= al[mi][1]; o[mi][nt][3] *= al[mi][1];
                    }
            }

            uint32_t p01[2][8], p23[2][8];
            #pragma unroll
            for (int mi = 0; mi < 2; mi++)
                #pragma unroll
                for (int nt = 0; nt < 8; nt++) {
                    p01[mi][nt] = ex2_h2(s[mi][nt][0] - mm[mi][0],
                                         s[mi][nt][1] - mm[mi][0]);
                    p23[mi][nt] = ex2_h2(s[mi][nt][2] - mm[mi][1],
                                         s[mi][nt][3] - mm[mi][1]);
                }

            uint32_t bb[2][8][2];
            load_vfrags(cur, j, 0, bb[0]);
            #pragma unroll
            for (int kt = 0; kt < 4; kt++) {
                int cf = kt & 1;
                if (kt < 3) load_vfrags(cur, j, kt + 1, bb[cf ^ 1]);
                #pragma unroll
                for (int mi = 0; mi < 2; mi++) {
                    uint32_t a0 = p01[mi][2 * kt],     a1 = p23[mi][2 * kt];
                    uint32_t a2 = p01[mi][2 * kt + 1], a3 = p23[mi][2 * kt + 1];
                    #pragma unroll
                    for (int nt = 0; nt < 8; nt++)
                        mma_f16(o[mi][nt], a0, a1, a2, a3, bb[cf][nt][0], bb[cf][nt][1]);
                    mma_f16(o[mi][8], a0, a1, a2, a3, lfrag, lfrag);
                }
            }
        }
    }

    #pragma unroll
    for (int mi = 0; mi < 2; mi++) {
        float l0 = __shfl_sync(0xffffffffu, o[mi][8][0], lane & 28);
        float l1 = __shfl_sync(0xffffffffu, o[mi][8][2], lane & 28);
        float inv0 = 1.f / l0, inv1 = 1.f / l1;
        int row0 = qb * 128 + warp * 32 + mi * 16 + lr;
        __half* op0 = Out + (size_t)row0 * EDIM + h * 64;
        __half* op1 = op0 + (size_t)8 * EDIM;
        #pragma unroll
        for (int nt = 0; nt < 8; nt++) {
            int col = nt * 8 + 2 * lc;
            *(__half2*)(op0 + col) = __floats2half2_rn(o[mi][nt][0] * inv0,
                                                       o[mi][nt][1] * inv0);
            *(__half2*)(op1 + col) = __floats2half2_rn(o[mi][nt][2] * inv1,
                                                       o[mi][nt][3] * inv1);
        }
    }
}

// ---------------------------------------------------------------------------
extern "C" void kernel_launch(void* const* d_in, const int* in_sizes, int n_in,
                              void* d_out, int out_size)
{
    const float* x  = (const float*)d_in[0];
    const float* W1 = (const float*)d_in[1];
    const float* b1 = (const float*)d_in[2];
    const float* W2 = (const float*)d_in[3];
    const float* b2 = (const float*)d_in[4];
    float* out = (float*)d_out;

    __half *QKVbuf, *Abuf, *Xbuf, *W1Tbuf, *W2Tbuf;
    cudaGetSymbolAddress((void**)&QKVbuf, g_QKV);
    cudaGetSymbolAddress((void**)&Abuf,   g_ATT);
    cudaGetSymbolAddress((void**)&Xbuf,   g_X);
    cudaGetSymbolAddress((void**)&W1Tbuf, g_W1T);
    cudaGetSymbolAddress((void**)&W2Tbuf, g_W2T);

    const int gemm_smem = 3 * 2 * 128 * 72 * 2;          // 110592 B
    const int attn_smem = 5 * 128 * 72 * 2;              // 92160 B

    // one-time setup (first call = correctness run, not captured)
    static bool init_done = false;
    static cudaStream_t sAttn, sProj;
    static cudaEvent_t evG[NB], evA[NB], evC[NB];
    if (!init_done) {
        cudaFuncSetAttribute(gemm_f16<0>,
                             cudaFuncAttributeMaxDynamicSharedMemorySize, gemm_smem);
        cudaFuncSetAttribute(gemm_f16<1>,
                             cudaFuncAttributeMaxDynamicSharedMemorySize, gemm_smem);
        cudaFuncSetAttribute(attn_f16,
                             cudaFuncAttributeMaxDynamicSharedMemorySize, attn_smem);
        cudaStreamCreateWithFlags(&sAttn, cudaStreamNonBlocking);
        cudaStreamCreateWithFlags(&sProj, cudaStreamNonBlocking);
        for (int b = 0; b < NB; b++) {
            cudaEventCreateWithFlags(&evG[b], cudaEventDisableTiming);
            cudaEventCreateWithFlags(&evA[b], cudaEventDisableTiming);
            cudaEventCreateWithFlags(&evC[b], cudaEventDisableTiming);
        }
        init_done = true;
    }

    // pre-pass on main stream
    prepass<<<XB + W1B + W2B, 256>>>(x, W1, W2, Xbuf, W1Tbuf, W2Tbuf);

    // GEMM1 split into NB batch chunks on main stream; event after each
    for (int b = 0; b < NB; b++) {
        const __half* Ab = Xbuf + (size_t)b * SEQ * EDIM;
        __half* Cb = QKVbuf + (size_t)b * SEQ * H3;
        gemm_f16<1><<<dim3(H3 / 128, SEQ / 128), 128, gemm_smem>>>(
            Ab, W1Tbuf, b1, Cb, SEQ, H3, EDIM);
        cudaEventRecord(evG[b], 0);
    }

    // attention per batch on sAttn (waits on its GEMM1 chunk)
    for (int b = 0; b < NB; b++) {
        cudaStreamWaitEvent(sAttn, evG[b], 0);
        attn_f16<<<dim3(SEQ / 128, NH, 1), 128, attn_smem, sAttn>>>(
            QKVbuf + (size_t)b * SEQ * H3, Abuf + (size_t)b * SEQ * EDIM);
        cudaEventRecord(evA[b], sAttn);
    }

    // output projection per batch on sProj (waits on its attention chunk)
    for (int b = 0; b < NB; b++) {
        cudaStreamWaitEvent(sProj, evA[b], 0);
        gemm_f16<0><<<dim3(EDIM / 128, SEQ / 128), 128, gemm_smem, sProj>>>(
            Abuf + (size_t)b * SEQ * EDIM, W2Tbuf, b2,
            out + (size_t)b * SEQ * EDIM, SEQ, EDIM, EDIM);
        cudaEventRecord(evC[b], sProj);
    }

    // join forks back into the main (capture) stream
    for (int b = 0; b < NB; b++)
        cudaStreamWaitEvent(0, evC[b], 0);
}

// round 16
// speedup vs baseline: 1.0552x; 1.0552x over previous
#include <cuda_runtime.h>
#include <cuda_fp16.h>
#include <cstdint>

#define NB   4
#define SEQ  2048
#define EDIM 1024
#define H3   3072
#define NH   16
#define NTOK (NB*SEQ)

// Q pre-scale: (1/sqrt(64)) * log2(e)  -> scores land in log2 domain
#define QSCALE 0.180336880111120432f

// Scratch (device globals: allocation-free, graph-capture safe)
__device__ __half g_QKV[(size_t)NTOK * H3];    // [token][Qall(scaled)|Kall|Vall]
__device__ __half g_ATT[(size_t)NTOK * EDIM];  // attention out
__device__ __half g_X  [(size_t)NTOK * EDIM];  // x in half
__device__ __half g_W1T[(size_t)H3   * EDIM];  // W1^T, rows permuted [Q|K|V]
__device__ __half g_W2T[(size_t)EDIM * EDIM];  // W2^T

__device__ __forceinline__ void mma_f16(float d[4],
                                        uint32_t a0, uint32_t a1, uint32_t a2, uint32_t a3,
                                        uint32_t b0, uint32_t b1) {
    asm volatile(
        "mma.sync.aligned.m16n8k16.row.col.f32.f16.f16.f32 "
        "{%0,%1,%2,%3}, {%4,%5,%6,%7}, {%8,%9}, {%0,%1,%2,%3};"
        : "+f"(d[0]), "+f"(d[1]), "+f"(d[2]), "+f"(d[3])
        : "r"(a0), "r"(a1), "r"(a2), "r"(a3), "r"(b0), "r"(b1));
}
// f16 accumulator variant (QK only): c[0]={row lr, cols 2lc,2lc+1}, c[1]=row lr+8
__device__ __forceinline__ void mma_f16h(uint32_t c[2],
                                         uint32_t a0, uint32_t a1, uint32_t a2, uint32_t a3,
                                         uint32_t b0, uint32_t b1) {
    asm volatile(
        "mma.sync.aligned.m16n8k16.row.col.f16.f16.f16.f16 "
        "{%0,%1}, {%2,%3,%4,%5}, {%6,%7}, {%0,%1};"
        : "+r"(c[0]), "+r"(c[1])
        : "r"(a0), "r"(a1), "r"(a2), "r"(a3), "r"(b0), "r"(b1));
}
__device__ __forceinline__ uint32_t smaddr(const void* p) {
    return (uint32_t)__cvta_generic_to_shared(p);
}
__device__ __forceinline__ void ldsm_x4(uint32_t r[4], uint32_t addr) {
    asm volatile("ldmatrix.sync.aligned.m8n8.x4.shared.b16 {%0,%1,%2,%3}, [%4];"
                 : "=r"(r[0]), "=r"(r[1]), "=r"(r[2]), "=r"(r[3]) : "r"(addr));
}
__device__ __forceinline__ void ldsm_x4_t(uint32_t r[4], uint32_t addr) {
    asm volatile("ldmatrix.sync.aligned.m8n8.x4.trans.shared.b16 {%0,%1,%2,%3}, [%4];"
                 : "=r"(r[0]), "=r"(r[1]), "=r"(r[2]), "=r"(r[3]) : "r"(addr));
}
__device__ __forceinline__ void cp16(uint32_t dst, const void* src) {
    asm volatile("cp.async.cg.shared.global [%0], [%1], 16;\n" :: "r"(dst), "l"(src));
}
#define CP_COMMIT()  asm volatile("cp.async.commit_group;\n" ::: "memory")
#define CP_WAIT(n)   asm volatile("cp.async.wait_group %0;\n" :: "n"(n) : "memory")

__device__ __forceinline__ float ex2(float x) {
    float y;
    asm("ex2.approx.ftz.f32 %0, %1;" : "=f"(y) : "f"(x));
    return y;
}
// packed half2 2^x
__device__ __forceinline__ uint32_t ex2_f16x2(uint32_t x) {
    uint32_t r;
    asm("ex2.approx.f16x2 %0, %1;" : "=r"(r) : "r"(x));
    return r;
}
__device__ __forceinline__ uint32_t hsub2u(uint32_t a, uint32_t b) {
    uint32_t r;
    asm("sub.f16x2 %0, %1, %2;" : "=r"(r) : "r"(a), "r"(b));
    return r;
}
__device__ __forceinline__ uint32_t hmax2u(uint32_t a, uint32_t b) {
    uint32_t r;
    asm("max.f16x2 %0, %1, %2;" : "=r"(r) : "r"(a), "r"(b));
    return r;
}
__device__ __forceinline__ uint32_t h2u(__half2 h) {
    union { __half2 h; uint32_t u; } c; c.h = h; return c.u;
}
__device__ __forceinline__ __half2 u2h(uint32_t u) {
    union { __half2 h; uint32_t u; } c; c.u = u; return c.h;
}

// ---------------------------------------------------------------------------
// Merged pre-pass: block ranges dispatch x-convert / W1 trans / W2 trans.
// ---------------------------------------------------------------------------
#define XB   (NTOK * EDIM / 4 / 256)        // 8192
#define W1B  ((H3 / 32) * (EDIM / 32))      // 3072
#define W2B  ((EDIM / 32) * (EDIM / 32))    // 1024

__global__ __launch_bounds__(256)
void prepass(const float* __restrict__ x, const float* __restrict__ W1,
             const float* __restrict__ W2, __half* __restrict__ Xh,
             __half* __restrict__ W1T, __half* __restrict__ W2T)
{
    __shared__ float t[32][33];
    int bid = blockIdx.x;
    if (bid < XB) {
        int i = bid * 256 + threadIdx.x;
        float4 v = ((const float4*)x)[i];
        uint2 o;
        o.x = h2u(__floats2half2_rn(v.x, v.y));
        o.y = h2u(__floats2half2_rn(v.z, v.w));
        ((uint2*)Xh)[i] = o;
        return;
    }
    const float* W;
    __half* WT;
    int NC, K = EDIM;
    bool perm;
    int idx;
    if (bid < XB + W1B) {
        idx = bid - XB; W = W1; WT = W1T; NC = H3; perm = true;
    } else {
        idx = bid - XB - W1B; W = W2; WT = W2T; NC = EDIM; perm = false;
    }
    int nbx = NC / 32;
    int bx = idx % nbx, by = idx / nbx;
    int tx = threadIdx.x & 31, ty = threadIdx.x >> 5;
    int c0 = bx * 32, k0 = by * 32;
    #pragma unroll
    for (int i = 0; i < 32; i += 8)
        t[ty + i][tx] = W[(size_t)(k0 + ty + i) * NC + c0 + tx];
    __syncthreads();
    int cbase = perm ? ((c0 % 192) / 64) * 1024 + (c0 / 192) * 64 + (c0 % 64) : c0;
    #pragma unroll
    for (int i = 0; i < 32; i += 8) {
        int j = ty + i;
        WT[(size_t)(cbase + j) * K + k0 + tx] = __float2half_rn(t[tx][j]);
    }
}

// ---------------------------------------------------------------------------
// FP16 GEMM (unchanged from R14)
// ---------------------------------------------------------------------------
template<int MODE>
__global__ __launch_bounds__(128, 2)
void gemm_f16(const __half* __restrict__ A, const __half* __restrict__ Bt,
              const float* __restrict__ bias, void* __restrict__ Cout,
              int M, int Nstride, int K)
{
    extern __shared__ __half sh[];
    __half (*As)[128][72] = (__half (*)[128][72])sh;                 // 3 stages
    __half (*Bs)[128][72] = (__half (*)[128][72])(sh + 3 * 128 * 72);

    const int tid  = threadIdx.x;
    const int bm   = blockIdx.y, bn = blockIdx.x;
    const int warp = tid >> 5, lane = tid & 31;
    const int wm   = (warp >> 1) * 64;
    const int wn   = (warp & 1) * 64;
    const int lr   = lane >> 2, lc = lane & 3;

    const int arow = wm + ((lane >> 3) & 1) * 8 + (lane & 7);
    const int ach  = ((lane >> 4) & 1) * 8;
    const int brow = wn + ((lane >> 4) & 1) * 8 + (lane & 7);
    const int bch  = ((lane >> 3) & 1) * 8;

    const int ntiles = K >> 6;

    float d[4][8][4];
    #pragma unroll
    for (int mt = 0; mt < 4; mt++)
        #pragma unroll
        for (int nt = 0; nt < 8; nt++)
            #pragma unroll
            for (int r = 0; r < 4; r++) d[mt][nt][r] = 0.f;

    auto prefetch = [&](int t, int buf) {
        int k0 = t << 6;
        #pragma unroll
        for (int i = 0; i < 8; i++) {
            int idx = i * 128 + tid;
            int r = idx >> 3, c = idx & 7;
            cp16(smaddr(&As[buf][r][c * 8]), A  + (size_t)(bm * 128 + r) * K + k0 + c * 8);
        }
        #pragma unroll
        for (int i = 0; i < 8; i++) {
            int idx = i * 128 + tid;
            int r = idx >> 3, c = idx & 7;
            cp16(smaddr(&Bs[buf][r][c * 8]), Bt + (size_t)(bn * 128 + r) * K + k0 + c * 8);
        }
        CP_COMMIT();
    };

    auto load_frags = [&](int cur, int kt, uint32_t (&a)[4][4], uint32_t (&b)[8][2]) {
        #pragma unroll
        for (int mt = 0; mt < 4; mt++)
            ldsm_x4(a[mt], smaddr(&As[cur][arow + mt * 16][kt * 16 + ach]));
        #pragma unroll
        for (int ntp = 0; ntp < 4; ntp++) {
            uint32_t t4[4];
            ldsm_x4(t4, smaddr(&Bs[cur][brow + ntp * 16][kt * 16 + bch]));
            b[2 * ntp][0] = t4[0]; b[2 * ntp][1] = t4[1];
            b[2 * ntp + 1][0] = t4[2]; b[2 * ntp + 1][1] = t4[3];
        }
    };

    prefetch(0, 0);
    prefetch(1, 1);

    for (int t = 0; t < ntiles; t++) {
        int cur = t % 3;
        if (t + 1 < ntiles) { CP_WAIT(1); } else { CP_WAIT(0); }
        __syncthreads();
        if (t + 2 < ntiles) prefetch(t + 2, (t + 2) % 3);

        uint32_t a[2][4][4], b[2][8][2];
        load_frags(cur, 0, a[0], b[0]);
        #pragma unroll
        for (int kt = 0; kt < 4; kt++) {
            int cf = kt & 1;
            if (kt < 3) load_frags(cur, kt + 1, a[cf ^ 1], b[cf ^ 1]);
            #pragma unroll
            for (int mt = 0; mt < 4; mt++)
                #pragma unroll
                for (int nt = 0; nt < 8; nt++)
                    mma_f16(d[mt][nt], a[cf][mt][0], a[cf][mt][1],
                            a[cf][mt][2], a[cf][mt][3], b[cf][nt][0], b[cf][nt][1]);
        }
    }

    #pragma unroll
    for (int mt = 0; mt < 4; mt++) {
        #pragma unroll
        for (int nt = 0; nt < 8; nt++) {
            int row  = bm * 128 + wm + mt * 16 + lr;
            int colg = bn * 128 + wn + nt * 8 + 2 * lc;
            float2 bv;
            if (MODE == 1) {
                int map = ((colg & 1023) >> 6) * 192 + (colg >> 10) * 64 + (colg & 63);
                bv = *(const float2*)(bias + map);
            } else {
                bv = *(const float2*)(bias + colg);
            }
            float e0 = d[mt][nt][0] + bv.x, e1 = d[mt][nt][1] + bv.y;
            float e2 = d[mt][nt][2] + bv.x, e3 = d[mt][nt][3] + bv.y;
            if (MODE == 0) {
                float* C = (float*)Cout;
                *(float2*)(C + (size_t)row * Nstride + colg)       = make_float2(e0, e1);
                *(float2*)(C + (size_t)(row + 8) * Nstride + colg) = make_float2(e2, e3);
            } else {
                float s = (colg < 1024) ? QSCALE : 1.0f;
                __half* C = (__half*)Cout;
                *(__half2*)(C + (size_t)row * Nstride + colg) =
                    __floats2half2_rn(e0 * s, e1 * s);
                *(__half2*)(C + (size_t)(row + 8) * Nstride + colg) =
                    __floats2half2_rn(e2 * s, e3 * s);
            }
        }
    }
}

// ---------------------------------------------------------------------------
// Flash attention. QK uses f16-ACCUMULATOR mma (scores tiny, K=64); softmax
// runs packed (HMAX2 scan, HSUB2 + ex2.f16x2 -> P, zero cvt). PV stays
// fp32-acc. l via constant ones-fragment. Online softmax in fp32 stats.
// grid=(SEQ/128, NH, NB), block=128 (4 warps x 32 q-rows).
// smem: Qs[128][72] | Ks[2][128][72] | Vs[2][128][72]  = 92160 B
// ---------------------------------------------------------------------------
__global__ __launch_bounds__(128, 2)
void attn_f16(const __half* __restrict__ Qkv, __half* __restrict__ Out)
{
    extern __shared__ __half smp[];
    __half* Qs = smp;                                          // [128][72]
    __half (*Ks)[128][72] = (__half (*)[128][72])(smp + 128 * 72);
    __half (*Vs)[128][72] = (__half (*)[128][72])(smp + 128 * 72 + 2 * 128 * 72);

    const int qb = blockIdx.x, h = blockIdx.y, n = blockIdx.z;
    const int tid = threadIdx.x, warp = tid >> 5, lane = tid & 31;
    const int lr = lane >> 2, lc = lane & 3;

    const __half* Qbase = Qkv + (size_t)(n * SEQ) * H3 + h * 64;
    const __half* Kbase = Qbase + 1024;
    const __half* Vbase = Qbase + 2048;

    const int ar  = warp * 32 + ((lane >> 3) & 1) * 8 + (lane & 7);
    const int ach = ((lane >> 4) & 1) * 8;
    const int br  = ((lane >> 4) & 1) * 8 + (lane & 7);
    const int bch = ((lane >> 3) & 1) * 8;
    const int vtr = ((lane >> 3) & 1) * 8 + (lane & 7);
    const int vtc = ((lane >> 4) & 1) * 8;

    const uint32_t lfrag = (lr == 0) ? 0x3C003C00u : 0u;

    auto prefetch_kv = [&](int t, int buf) {
        #pragma unroll
        for (int i = 0; i < 8; i++) {
            int idx = i * 128 + tid;
            int r = idx >> 3, c = idx & 7;
            cp16(smaddr(&Ks[buf][r][c * 8]),
                 Kbase + (size_t)(t * 128 + r) * H3 + c * 8);
            cp16(smaddr(&Vs[buf][r][c * 8]),
                 Vbase + (size_t)(t * 128 + r) * H3 + c * 8);
        }
        CP_COMMIT();
    };

    auto load_vfrags = [&](int cur, int j, int kt, uint32_t (&bb)[8][2]) {
        #pragma unroll
        for (int ntp = 0; ntp < 4; ntp++) {
            uint32_t t4[4];
            ldsm_x4_t(t4, smaddr(&Vs[cur][j * 64 + kt * 16 + vtr][ntp * 16 + vtc]));
            bb[2 * ntp][0] = t4[0]; bb[2 * ntp][1] = t4[1];
            bb[2 * ntp + 1][0] = t4[2]; bb[2 * ntp + 1][1] = t4[3];
        }
    };

    #pragma unroll
    for (int i = 0; i < 8; i++) {
        int idx = i * 128 + tid;
        int r = idx >> 3, c = idx & 7;
        cp16(smaddr(&Qs[r * 72 + c * 8]),
             Qbase + (size_t)(qb * 128 + r) * H3 + c * 8);
    }
    prefetch_kv(0, 0);

    CP_WAIT(0);
    __syncthreads();

    uint32_t aq[4][2][4];
    #pragma unroll
    for (int kt = 0; kt < 4; kt++)
        #pragma unroll
        for (int mi = 0; mi < 2; mi++)
            ldsm_x4(aq[kt][mi], smaddr(&Qs[(ar + mi * 16) * 72 + kt * 16 + ach]));

    float o[2][9][4];
    #pragma unroll
    for (int mi = 0; mi < 2; mi++)
        #pragma unroll
        for (int nt = 0; nt < 9; nt++)
            #pragma unroll
            for (int r = 0; r < 4; r++) o[mi][nt][r] = 0.f;
    float mm[2][2] = {{-1e30f, -1e30f}, {-1e30f, -1e30f}};

    const int NT = SEQ / 128;
    for (int t = 0; t < NT; t++) {
        int cur = t & 1;
        if (t > 0) {
            CP_WAIT(0);
            __syncthreads();
        }
        if (t + 1 < NT) prefetch_kv(t + 1, cur ^ 1);

        #pragma unroll
        for (int j = 0; j < 2; j++) {
            // S = Q @ K^T (log2 domain), f16 accumulators
            uint32_t sh2[2][8][2];
            #pragma unroll
            for (int mi = 0; mi < 2; mi++)
                #pragma unroll
                for (int nt = 0; nt < 8; nt++) { sh2[mi][nt][0] = 0; sh2[mi][nt][1] = 0; }
            uint32_t kb[2][8][2];
            {
                uint32_t t4[4];
                #pragma unroll
                for (int ntp = 0; ntp < 4; ntp++) {
                    ldsm_x4(t4, smaddr(&Ks[cur][j * 64 + br + ntp * 16][bch]));
                    kb[0][2 * ntp][0] = t4[0]; kb[0][2 * ntp][1] = t4[1];
                    kb[0][2 * ntp + 1][0] = t4[2]; kb[0][2 * ntp + 1][1] = t4[3];
                }
            }
            #pragma unroll
            for (int kt = 0; kt < 4; kt++) {
                int cf = kt & 1;
                if (kt < 3) {
                    uint32_t t4[4];
                    #pragma unroll
                    for (int ntp = 0; ntp < 4; ntp++) {
                        ldsm_x4(t4, smaddr(&Ks[cur][j * 64 + br + ntp * 16]
                                                   [(kt + 1) * 16 + bch]));
                        kb[cf ^ 1][2 * ntp][0] = t4[0];
                        kb[cf ^ 1][2 * ntp][1] = t4[1];
                        kb[cf ^ 1][2 * ntp + 1][0] = t4[2];
                        kb[cf ^ 1][2 * ntp + 1][1] = t4[3];
                    }
                }
                #pragma unroll
                for (int mi = 0; mi < 2; mi++)
                    #pragma unroll
                    for (int nt = 0; nt < 8; nt++)
                        mma_f16h(sh2[mi][nt], aq[kt][mi][0], aq[kt][mi][1],
                                 aq[kt][mi][2], aq[kt][mi][3],
                                 kb[cf][nt][0], kb[cf][nt][1]);
            }

            // packed softmax stats: HMAX2 scan, fp32 running max bookkeeping
            float al[2][2];
            #pragma unroll
            for (int mi = 0; mi < 2; mi++) {
                uint32_t h0 = sh2[mi][0][0], h1 = sh2[mi][0][1];
                #pragma unroll
                for (int nt = 1; nt < 8; nt++) {
                    h0 = hmax2u(h0, sh2[mi][nt][0]);
                    h1 = hmax2u(h1, sh2[mi][nt][1]);
                }
                float2 f0 = __half22float2(u2h(h0));
                float2 f1 = __half22float2(u2h(h1));
                float mx0 = fmaxf(f0.x, f0.y), mx1 = fmaxf(f1.x, f1.y);
                mx0 = fmaxf(mx0, __shfl_xor_sync(0xffffffffu, mx0, 1));
                mx0 = fmaxf(mx0, __shfl_xor_sync(0xffffffffu, mx0, 2));
                mx1 = fmaxf(mx1, __shfl_xor_sync(0xffffffffu, mx1, 1));
                mx1 = fmaxf(mx1, __shfl_xor_sync(0xffffffffu, mx1, 2));
                float nm0 = fmaxf(mm[mi][0], mx0), nm1 = fmaxf(mm[mi][1], mx1);
                al[mi][0] = ex2(mm[mi][0] - nm0);
                al[mi][1] = ex2(mm[mi][1] - nm1);
                mm[mi][0] = nm0; mm[mi][1] = nm1;
            }
            if (!__all_sync(0xffffffffu,
                            (al[0][0] == 1.f) && (al[0][1] == 1.f) &&
                            (al[1][0] == 1.f) && (al[1][1] == 1.f))) {
                #pragma unroll
                for (int mi = 0; mi < 2; mi++)
                    #pragma unroll
                    for (int nt = 0; nt < 9; nt++) {
                        o[mi][nt][0] *= al[mi][0]; o[mi][nt][1] *= al[mi][0];
                        o[mi][nt][2] *= al[mi][1]; o[mi][nt][3] *= al[mi][1];
                    }
            }

            // P = 2^(s - m): packed HSUB2 + ex2.f16x2, straight to A-frags
            uint32_t p01[2][8], p23[2][8];
            #pragma unroll
            for (int mi = 0; mi < 2; mi++) {
                uint32_t m0h = h2u(__half2half2(__float2half_rn(mm[mi][0])));
                uint32_t m1h = h2u(__half2half2(__float2half_rn(mm[mi][1])));
                #pragma unroll
                for (int nt = 0; nt < 8; nt++) {
                    p01[mi][nt] = ex2_f16x2(hsub2u(sh2[mi][nt][0], m0h));
                    p23[mi][nt] = ex2_f16x2(hsub2u(sh2[mi][nt][1], m1h));
                }
            }

            // O += P @ V ; l via constant ones-fragment (nt=8)
            uint32_t bb[2][8][2];
            load_vfrags(cur, j, 0, bb[0]);
            #pragma unroll
            for (int kt = 0; kt < 4; kt++) {
                int cf = kt & 1;
                if (kt < 3) load_vfrags(cur, j, kt + 1, bb[cf ^ 1]);
                #pragma unroll
                for (int mi = 0; mi < 2; mi++) {
                    uint32_t a0 = p01[mi][2 * kt],     a1 = p23[mi][2 * kt];
                    uint32_t a2 = p01[mi][2 * kt + 1], a3 = p23[mi][2 * kt + 1];
                    #pragma unroll
                    for (int nt = 0; nt < 8; nt++)
                        mma_f16(o[mi][nt], a0, a1, a2, a3, bb[cf][nt][0], bb[cf][nt][1]);
                    mma_f16(o[mi][8], a0, a1, a2, a3, lfrag, lfrag);
                }
            }
        }
    }

    #pragma unroll
    for (int mi = 0; mi < 2; mi++) {
        float l0 = __shfl_sync(0xffffffffu, o[mi][8][0], lane & 28);
        float l1 = __shfl_sync(0xffffffffu, o[mi][8][2], lane & 28);
        float inv0 = 1.f / l0, inv1 = 1.f / l1;
        int row0 = qb * 128 + warp * 32 + mi * 16 + lr;
        __half* op0 = Out + (size_t)(n * SEQ + row0) * EDIM + h * 64;
        __half* op1 = op0 + (size_t)8 * EDIM;
        #pragma unroll
        for (int nt = 0; nt < 8; nt++) {
            int col = nt * 8 + 2 * lc;
            *(__half2*)(op0 + col) = __floats2half2_rn(o[mi][nt][0] * inv0,
                                                       o[mi][nt][1] * inv0);
            *(__half2*)(op1 + col) = __floats2half2_rn(o[mi][nt][2] * inv1,
                                                       o[mi][nt][3] * inv1);
        }
    }
}

// ---------------------------------------------------------------------------
extern "C" void kernel_launch(void* const* d_in, const int* in_sizes, int n_in,
                              void* d_out, int out_size)
{
    const float* x  = (const float*)d_in[0];
    const float* W1 = (const float*)d_in[1];
    const float* b1 = (const float*)d_in[2];
    const float* W2 = (const float*)d_in[3];
    const float* b2 = (const float*)d_in[4];
    float* out = (float*)d_out;

    __half *QKVbuf, *Abuf, *Xbuf, *W1Tbuf, *W2Tbuf;
    cudaGetSymbolAddress((void**)&QKVbuf, g_QKV);
    cudaGetSymbolAddress((void**)&Abuf,   g_ATT);
    cudaGetSymbolAddress((void**)&Xbuf,   g_X);
    cudaGetSymbolAddress((void**)&W1Tbuf, g_W1T);
    cudaGetSymbolAddress((void**)&W2Tbuf, g_W2T);

    const int gemm_smem = 3 * 2 * 128 * 72 * 2;          // 110592 B
    const int attn_smem = 5 * 128 * 72 * 2;              // 92160 B
    static bool attr_done = false;
    if (!attr_done) {
        cudaFuncSetAttribute(gemm_f16<0>,
                             cudaFuncAttributeMaxDynamicSharedMemorySize, gemm_smem);
        cudaFuncSetAttribute(gemm_f16<1>,
                             cudaFuncAttributeMaxDynamicSharedMemorySize, gemm_smem);
        cudaFuncSetAttribute(attn_f16,
                             cudaFuncAttributeMaxDynamicSharedMemorySize, attn_smem);
        attr_done = true;
    }

    // merged pre-pass: x -> half; W1 -> permuted W1T; W2 -> W2T
    prepass<<<XB + W1B + W2B, 256>>>(x, W1, W2, Xbuf, W1Tbuf, W2Tbuf);

    // 1) QKV projection: Q(scaled)|K|V rows -> g_QKV
    gemm_f16<1><<<dim3(H3 / 128, NTOK / 128), 128, gemm_smem>>>(
        Xbuf, W1Tbuf, b1, QKVbuf, NTOK, H3, EDIM);
    // 2) attention -> g_ATT (half)
    attn_f16<<<dim3(SEQ / 128, NH, NB), 128, attn_smem>>>(QKVbuf, Abuf);
    // 3) output projection -> fp32 out
    gemm_f16<0><<<dim3(EDIM / 128, NTOK / 128), 128, gemm_smem>>>(
        Abuf, W2Tbuf, b2, out, NTOK, EDIM, EDIM);
}

// round 17
// speedup vs baseline: 1.0836x; 1.0269x over previous
#include <cuda_runtime.h>
#include <cuda_fp16.h>
#include <cstdint>

#define NB   4
#define SEQ  2048
#define EDIM 1024
#define H3   3072
#define NH   16
#define NTOK (NB*SEQ)

#define QSCALE 0.180336880111120432f

// grid segmentation of the fused kernel
#define G1N  1536   // GEMM1: 64 m-tiles x 24 n-tiles
#define ATN  1024   // attention: 4 batches x 16 qb x 16 heads
#define G2N  512    // GEMM2: 64 m-tiles x 8 n-tiles

// Scratch (device globals: allocation-free, graph-capture safe)
__device__ __half g_QKV[(size_t)NTOK * H3];
__device__ __half g_ATT[(size_t)NTOK * EDIM];
__device__ __half g_X  [(size_t)NTOK * EDIM];
__device__ __half g_W1T[(size_t)H3   * EDIM];
__device__ __half g_W2T[(size_t)EDIM * EDIM];
__device__ int    g_cnt1[NB];
__device__ int    g_cnt2[NB];

__device__ __forceinline__ void mma_f16(float d[4],
                                        uint32_t a0, uint32_t a1, uint32_t a2, uint32_t a3,
                                        uint32_t b0, uint32_t b1) {
    asm volatile(
        "mma.sync.aligned.m16n8k16.row.col.f32.f16.f16.f32 "
        "{%0,%1,%2,%3}, {%4,%5,%6,%7}, {%8,%9}, {%0,%1,%2,%3};"
        : "+f"(d[0]), "+f"(d[1]), "+f"(d[2]), "+f"(d[3])
        : "r"(a0), "r"(a1), "r"(a2), "r"(a3), "r"(b0), "r"(b1));
}
__device__ __forceinline__ void mma_f16h(uint32_t c[2],
                                         uint32_t a0, uint32_t a1, uint32_t a2, uint32_t a3,
                                         uint32_t b0, uint32_t b1) {
    asm volatile(
        "mma.sync.aligned.m16n8k16.row.col.f16.f16.f16.f16 "
        "{%0,%1}, {%2,%3,%4,%5}, {%6,%7}, {%0,%1};"
        : "+r"(c[0]), "+r"(c[1])
        : "r"(a0), "r"(a1), "r"(a2), "r"(a3), "r"(b0), "r"(b1));
}
__device__ __forceinline__ uint32_t smaddr(const void* p) {
    return (uint32_t)__cvta_generic_to_shared(p);
}
__device__ __forceinline__ void ldsm_x4(uint32_t r[4], uint32_t addr) {
    asm volatile("ldmatrix.sync.aligned.m8n8.x4.shared.b16 {%0,%1,%2,%3}, [%4];"
                 : "=r"(r[0]), "=r"(r[1]), "=r"(r[2]), "=r"(r[3]) : "r"(addr));
}
__device__ __forceinline__ void ldsm_x4_t(uint32_t r[4], uint32_t addr) {
    asm volatile("ldmatrix.sync.aligned.m8n8.x4.trans.shared.b16 {%0,%1,%2,%3}, [%4];"
                 : "=r"(r[0]), "=r"(r[1]), "=r"(r[2]), "=r"(r[3]) : "r"(addr));
}
__device__ __forceinline__ void cp16(uint32_t dst, const void* src) {
    asm volatile("cp.async.cg.shared.global [%0], [%1], 16;\n" :: "r"(dst), "l"(src));
}
#define CP_COMMIT()  asm volatile("cp.async.commit_group;\n" ::: "memory")
#define CP_WAIT(n)   asm volatile("cp.async.wait_group %0;\n" :: "n"(n) : "memory")

__device__ __forceinline__ float ex2(float x) {
    float y;
    asm("ex2.approx.ftz.f32 %0, %1;" : "=f"(y) : "f"(x));
    return y;
}
__device__ __forceinline__ uint32_t ex2_f16x2(uint32_t x) {
    uint32_t r;
    asm("ex2.approx.f16x2 %0, %1;" : "=r"(r) : "r"(x));
    return r;
}
__device__ __forceinline__ uint32_t hsub2u(uint32_t a, uint32_t b) {
    uint32_t r;
    asm("sub.f16x2 %0, %1, %2;" : "=r"(r) : "r"(a), "r"(b));
    return r;
}
__device__ __forceinline__ uint32_t hmax2u(uint32_t a, uint32_t b) {
    uint32_t r;
    asm("max.f16x2 %0, %1, %2;" : "=r"(r) : "r"(a), "r"(b));
    return r;
}
__device__ __forceinline__ uint32_t h2u(__half2 h) {
    union { __half2 h; uint32_t u; } c; c.h = h; return c.u;
}
__device__ __forceinline__ __half2 u2h(uint32_t u) {
    union { __half2 h; uint32_t u; } c; c.u = u; return c.h;
}

// ---------------------------------------------------------------------------
// Merged pre-pass (also zeroes dependency counters)
// ---------------------------------------------------------------------------
#define XB   (NTOK * EDIM / 4 / 256)        // 8192
#define W1B  ((H3 / 32) * (EDIM / 32))      // 3072
#define W2B  ((EDIM / 32) * (EDIM / 32))    // 1024

__global__ __launch_bounds__(256)
void prepass(const float* __restrict__ x, const float* __restrict__ W1,
             const float* __restrict__ W2)
{
    __shared__ float t[32][33];
    int bid = blockIdx.x;
    if (bid == 0 && threadIdx.x < 2 * NB) {
        if (threadIdx.x < NB) g_cnt1[threadIdx.x] = 0;
        else                  g_cnt2[threadIdx.x - NB] = 0;
    }
    if (bid < XB) {
        int i = bid * 256 + threadIdx.x;
        float4 v = ((const float4*)x)[i];
        uint2 o;
        o.x = h2u(__floats2half2_rn(v.x, v.y));
        o.y = h2u(__floats2half2_rn(v.z, v.w));
        ((uint2*)g_X)[i] = o;
        return;
    }
    const float* W;
    __half* WT;
    int NC, K = EDIM;
    bool perm;
    int idx;
    if (bid < XB + W1B) {
        idx = bid - XB; W = W1; WT = g_W1T; NC = H3; perm = true;
    } else {
        idx = bid - XB - W1B; W = W2; WT = g_W2T; NC = EDIM; perm = false;
    }
    int nbx = NC / 32;
    int bx = idx % nbx, by = idx / nbx;
    int tx = threadIdx.x & 31, ty = threadIdx.x >> 5;
    int c0 = bx * 32, k0 = by * 32;
    #pragma unroll
    for (int i = 0; i < 32; i += 8)
        t[ty + i][tx] = W[(size_t)(k0 + ty + i) * NC + c0 + tx];
    __syncthreads();
    int cbase = perm ? ((c0 % 192) / 64) * 1024 + (c0 / 192) * 64 + (c0 % 64) : c0;
    #pragma unroll
    for (int i = 0; i < 32; i += 8) {
        int j = ty + i;
        WT[(size_t)(cbase + j) * K + k0 + tx] = __float2half_rn(t[tx][j]);
    }
}

// ---------------------------------------------------------------------------
// GEMM body (device function; identical math to R16's gemm_f16)
// ---------------------------------------------------------------------------
template<int MODE>
__device__ __forceinline__
void gemm_body(const __half* __restrict__ A, const __half* __restrict__ Bt,
               const float* __restrict__ bias, void* __restrict__ Cout,
               int bm, int bn, int Nstride, int K, __half* sh)
{
    __half (*As)[128][72] = (__half (*)[128][72])sh;
    __half (*Bs)[128][72] = (__half (*)[128][72])(sh + 3 * 128 * 72);

    const int tid  = threadIdx.x;
    const int warp = tid >> 5, lane = tid & 31;
    const int wm   = (warp >> 1) * 64;
    const int wn   = (warp & 1) * 64;
    const int lr   = lane >> 2, lc = lane & 3;

    const int arow = wm + ((lane >> 3) & 1) * 8 + (lane & 7);
    const int ach  = ((lane >> 4) & 1) * 8;
    const int brow = wn + ((lane >> 4) & 1) * 8 + (lane & 7);
    const int bch  = ((lane >> 3) & 1) * 8;

    const int ntiles = K >> 6;

    float d[4][8][4];
    #pragma unroll
    for (int mt = 0; mt < 4; mt++)
        #pragma unroll
        for (int nt = 0; nt < 8; nt++)
            #pragma unroll
            for (int r = 0; r < 4; r++) d[mt][nt][r] = 0.f;

    auto prefetch = [&](int t, int buf) {
        int k0 = t << 6;
        #pragma unroll
        for (int i = 0; i < 8; i++) {
            int idx = i * 128 + tid;
            int r = idx >> 3, c = idx & 7;
            cp16(smaddr(&As[buf][r][c * 8]), A  + (size_t)(bm * 128 + r) * K + k0 + c * 8);
        }
        #pragma unroll
        for (int i = 0; i < 8; i++) {
            int idx = i * 128 + tid;
            int r = idx >> 3, c = idx & 7;
            cp16(smaddr(&Bs[buf][r][c * 8]), Bt + (size_t)(bn * 128 + r) * K + k0 + c * 8);
        }
        CP_COMMIT();
    };

    auto load_frags = [&](int cur, int kt, uint32_t (&a)[4][4], uint32_t (&b)[8][2]) {
        #pragma unroll
        for (int mt = 0; mt < 4; mt++)
            ldsm_x4(a[mt], smaddr(&As[cur][arow + mt * 16][kt * 16 + ach]));
        #pragma unroll
        for (int ntp = 0; ntp < 4; ntp++) {
            uint32_t t4[4];
            ldsm_x4(t4, smaddr(&Bs[cur][brow + ntp * 16][kt * 16 + bch]));
            b[2 * ntp][0] = t4[0]; b[2 * ntp][1] = t4[1];
            b[2 * ntp + 1][0] = t4[2]; b[2 * ntp + 1][1] = t4[3];
        }
    };

    prefetch(0, 0);
    prefetch(1, 1);

    for (int t = 0; t < ntiles; t++) {
        int cur = t % 3;
        if (t + 1 < ntiles) { CP_WAIT(1); } else { CP_WAIT(0); }
        __syncthreads();
        if (t + 2 < ntiles) prefetch(t + 2, (t + 2) % 3);

        uint32_t a[2][4][4], b[2][8][2];
        load_frags(cur, 0, a[0], b[0]);
        #pragma unroll
        for (int kt = 0; kt < 4; kt++) {
            int cf = kt & 1;
            if (kt < 3) load_frags(cur, kt + 1, a[cf ^ 1], b[cf ^ 1]);
            #pragma unroll
            for (int mt = 0; mt < 4; mt++)
                #pragma unroll
                for (int nt = 0; nt < 8; nt++)
                    mma_f16(d[mt][nt], a[cf][mt][0], a[cf][mt][1],
                            a[cf][mt][2], a[cf][mt][3], b[cf][nt][0], b[cf][nt][1]);
        }
    }

    #pragma unroll
    for (int mt = 0; mt < 4; mt++) {
        #pragma unroll
        for (int nt = 0; nt < 8; nt++) {
            int row  = bm * 128 + wm + mt * 16 + lr;
            int colg = bn * 128 + wn + nt * 8 + 2 * lc;
            float2 bv;
            if (MODE == 1) {
                int map = ((colg & 1023) >> 6) * 192 + (colg >> 10) * 64 + (colg & 63);
                bv = *(const float2*)(bias + map);
            } else {
                bv = *(const float2*)(bias + colg);
            }
            float e0 = d[mt][nt][0] + bv.x, e1 = d[mt][nt][1] + bv.y;
            float e2 = d[mt][nt][2] + bv.x, e3 = d[mt][nt][3] + bv.y;
            if (MODE == 0) {
                float* C = (float*)Cout;
                *(float2*)(C + (size_t)row * Nstride + colg)       = make_float2(e0, e1);
                *(float2*)(C + (size_t)(row + 8) * Nstride + colg) = make_float2(e2, e3);
            } else {
                float s = (colg < 1024) ? QSCALE : 1.0f;
                __half* C = (__half*)Cout;
                *(__half2*)(C + (size_t)row * Nstride + colg) =
                    __floats2half2_rn(e0 * s, e1 * s);
                *(__half2*)(C + (size_t)(row + 8) * Nstride + colg) =
                    __floats2half2_rn(e2 * s, e3 * s);
            }
        }
    }
}

// ---------------------------------------------------------------------------
// Attention body (device function; identical math to R16's attn_f16)
// ---------------------------------------------------------------------------
__device__ __forceinline__
void attn_body(const __half* __restrict__ Qkv, __half* __restrict__ Out,
               int qb, int h, __half* smp)
{
    __half* Qs = smp;
    __half (*Ks)[128][72] = (__half (*)[128][72])(smp + 128 * 72);
    __half (*Vs)[128][72] = (__half (*)[128][72])(smp + 128 * 72 + 2 * 128 * 72);

    const int tid = threadIdx.x, warp = tid >> 5, lane = tid & 31;
    const int lr = lane >> 2, lc = lane & 3;

    const __half* Qbase = Qkv + h * 64;
    const __half* Kbase = Qbase + 1024;
    const __half* Vbase = Qbase + 2048;

    const int ar  = warp * 32 + ((lane >> 3) & 1) * 8 + (lane & 7);
    const int ach = ((lane >> 4) & 1) * 8;
    const int br  = ((lane >> 4) & 1) * 8 + (lane & 7);
    const int bch = ((lane >> 3) & 1) * 8;
    const int vtr = ((lane >> 3) & 1) * 8 + (lane & 7);
    const int vtc = ((lane >> 4) & 1) * 8;

    const uint32_t lfrag = (lr == 0) ? 0x3C003C00u : 0u;

    auto prefetch_kv = [&](int t, int buf) {
        #pragma unroll
        for (int i = 0; i < 8; i++) {
            int idx = i * 128 + tid;
            int r = idx >> 3, c = idx & 7;
            cp16(smaddr(&Ks[buf][r][c * 8]),
                 Kbase + (size_t)(t * 128 + r) * H3 + c * 8);
            cp16(smaddr(&Vs[buf][r][c * 8]),
                 Vbase + (size_t)(t * 128 + r) * H3 + c * 8);
        }
        CP_COMMIT();
    };

    auto load_vfrags = [&](int cur, int j, int kt, uint32_t (&bb)[8][2]) {
        #pragma unroll
        for (int ntp = 0; ntp < 4; ntp++) {
            uint32_t t4[4];
            ldsm_x4_t(t4, smaddr(&Vs[cur][j * 64 + kt * 16 + vtr][ntp * 16 + vtc]));
            bb[2 * ntp][0] = t4[0]; bb[2 * ntp][1] = t4[1];
            bb[2 * ntp + 1][0] = t4[2]; bb[2 * ntp + 1][1] = t4[3];
        }
    };

    #pragma unroll
    for (int i = 0; i < 8; i++) {
        int idx = i * 128 + tid;
        int r = idx >> 3, c = idx & 7;
        cp16(smaddr(&Qs[r * 72 + c * 8]),
             Qbase + (size_t)(qb * 128 + r) * H3 + c * 8);
    }
    prefetch_kv(0, 0);

    CP_WAIT(0);
    __syncthreads();

    uint32_t aq[4][2][4];
    #pragma unroll
    for (int kt = 0; kt < 4; kt++)
        #pragma unroll
        for (int mi = 0; mi < 2; mi++)
            ldsm_x4(aq[kt][mi], smaddr(&Qs[(ar + mi * 16) * 72 + kt * 16 + ach]));

    float o[2][9][4];
    #pragma unroll
    for (int mi = 0; mi < 2; mi++)
        #pragma unroll
        for (int nt = 0; nt < 9; nt++)
            #pragma unroll
            for (int r = 0; r < 4; r++) o[mi][nt][r] = 0.f;
    float mm[2][2] = {{-1e30f, -1e30f}, {-1e30f, -1e30f}};

    const int NT = SEQ / 128;
    for (int t = 0; t < NT; t++) {
        int cur = t & 1;
        if (t > 0) {
            CP_WAIT(0);
            __syncthreads();
        }
        if (t + 1 < NT) prefetch_kv(t + 1, cur ^ 1);

        #pragma unroll
        for (int j = 0; j < 2; j++) {
            uint32_t sh2[2][8][2];
            #pragma unroll
            for (int mi = 0; mi < 2; mi++)
                #pragma unroll
                for (int nt = 0; nt < 8; nt++) { sh2[mi][nt][0] = 0; sh2[mi][nt][1] = 0; }
            uint32_t kb[2][8][2];
            {
                uint32_t t4[4];
                #pragma unroll
                for (int ntp = 0; ntp < 4; ntp++) {
                    ldsm_x4(t4, smaddr(&Ks[cur][j * 64 + br + ntp * 16][bch]));
                    kb[0][2 * ntp][0] = t4[0]; kb[0][2 * ntp][1] = t4[1];
                    kb[0][2 * ntp + 1][0] = t4[2]; kb[0][2 * ntp + 1][1] = t4[3];
                }
            }
            #pragma unroll
            for (int kt = 0; kt < 4; kt++) {
                int cf = kt & 1;
                if (kt < 3) {
                    uint32_t t4[4];
                    #pragma unroll
                    for (int ntp = 0; ntp < 4; ntp++) {
                        ldsm_x4(t4, smaddr(&Ks[cur][j * 64 + br + ntp * 16]
                                                   [(kt + 1) * 16 + bch]));
                        kb[cf ^ 1][2 * ntp][0] = t4[0];
                        kb[cf ^ 1][2 * ntp][1] = t4[1];
                        kb[cf ^ 1][2 * ntp + 1][0] = t4[2];
                        kb[cf ^ 1][2 * ntp + 1][1] = t4[3];
                    }
                }
                #pragma unroll
                for (int mi = 0; mi < 2; mi++)
                    #pragma unroll
                    for (int nt = 0; nt < 8; nt++)
                        mma_f16h(sh2[mi][nt], aq[kt][mi][0], aq[kt][mi][1],
                                 aq[kt][mi][2], aq[kt][mi][3],
                                 kb[cf][nt][0], kb[cf][nt][1]);
            }

            float al[2][2];
            #pragma unroll
            for (int mi = 0; mi < 2; mi++) {
                uint32_t h0 = sh2[mi][0][0], h1 = sh2[mi][0][1];
                #pragma unroll
                for (int nt = 1; nt < 8; nt++) {
                    h0 = hmax2u(h0, sh2[mi][nt][0]);
                    h1 = hmax2u(h1, sh2[mi][nt][1]);
                }
                float2 f0 = __half22float2(u2h(h0));
                float2 f1 = __half22float2(u2h(h1));
                float mx0 = fmaxf(f0.x, f0.y), mx1 = fmaxf(f1.x, f1.y);
                mx0 = fmaxf(mx0, __shfl_xor_sync(0xffffffffu, mx0, 1));
                mx0 = fmaxf(mx0, __shfl_xor_sync(0xffffffffu, mx0, 2));
                mx1 = fmaxf(mx1, __shfl_xor_sync(0xffffffffu, mx1, 1));
                mx1 = fmaxf(mx1, __shfl_xor_sync(0xffffffffu, mx1, 2));
                float nm0 = fmaxf(mm[mi][0], mx0), nm1 = fmaxf(mm[mi][1], mx1);
                al[mi][0] = ex2(mm[mi][0] - nm0);
                al[mi][1] = ex2(mm[mi][1] - nm1);
                mm[mi][0] = nm0; mm[mi][1] = nm1;
            }
            if (!__all_sync(0xffffffffu,
                            (al[0][0] == 1.f) && (al[0][1] == 1.f) &&
                            (al[1][0] == 1.f) && (al[1][1] == 1.f))) {
                #pragma unroll
                for (int mi = 0; mi < 2; mi++)
                    #pragma unroll
                    for (int nt = 0; nt < 9; nt++) {
                        o[mi][nt][0] *= al[mi][0]; o[mi][nt][1] *= al[mi][0];
                        o[mi][nt][2] *= al[mi][1]; o[mi][nt][3] *= al[mi][1];
                    }
            }

            uint32_t p01[2][8], p23[2][8];
            #pragma unroll
            for (int mi = 0; mi < 2; mi++) {
                uint32_t m0h = h2u(__half2half2(__float2half_rn(mm[mi][0])));
                uint32_t m1h = h2u(__half2half2(__float2half_rn(mm[mi][1])));
                #pragma unroll
                for (int nt = 0; nt < 8; nt++) {
                    p01[mi][nt] = ex2_f16x2(hsub2u(sh2[mi][nt][0], m0h));
                    p23[mi][nt] = ex2_f16x2(hsub2u(sh2[mi][nt][1], m1h));
                }
            }

            uint32_t bb[2][8][2];
            load_vfrags(cur, j, 0, bb[0]);
            #pragma unroll
            for (int kt = 0; kt < 4; kt++) {
                int cf = kt & 1;
                if (kt < 3) load_vfrags(cur, j, kt + 1, bb[cf ^ 1]);
                #pragma unroll
                for (int mi = 0; mi < 2; mi++) {
                    uint32_t a0 = p01[mi][2 * kt],     a1 = p23[mi][2 * kt];
                    uint32_t a2 = p01[mi][2 * kt + 1], a3 = p23[mi][2 * kt + 1];
                    #pragma unroll
                    for (int nt = 0; nt < 8; nt++)
                        mma_f16(o[mi][nt], a0, a1, a2, a3, bb[cf][nt][0], bb[cf][nt][1]);
                    mma_f16(o[mi][8], a0, a1, a2, a3, lfrag, lfrag);
                }
            }
        }
    }

    #pragma unroll
    for (int mi = 0; mi < 2; mi++) {
        float l0 = __shfl_sync(0xffffffffu, o[mi][8][0], lane & 28);
        float l1 = __shfl_sync(0xffffffffu, o[mi][8][2], lane & 28);
        float inv0 = 1.f / l0, inv1 = 1.f / l1;
        int row0 = qb * 128 + warp * 32 + mi * 16 + lr;
        __half* op0 = Out + (size_t)row0 * EDIM + h * 64;
        __half* op1 = op0 + (size_t)8 * EDIM;
        #pragma unroll
        for (int nt = 0; nt < 8; nt++) {
            int col = nt * 8 + 2 * lc;
            *(__half2*)(op0 + col) = __floats2half2_rn(o[mi][nt][0] * inv0,
                                                       o[mi][nt][1] * inv0);
            *(__half2*)(op1 + col) = __floats2half2_rn(o[mi][nt][2] * inv1,
                                                       o[mi][nt][3] * inv1);
        }
    }
}

// ---------------------------------------------------------------------------
// Fused pipeline kernel: [GEMM1 | attention | GEMM2] dispatched by blockIdx,
// dependencies enforced by per-batch counters (producer: fence + atomicAdd;
// consumer: volatile spin). Hardware dispatches CTAs in bid order, so
// producers always schedule before their consumers.
// ---------------------------------------------------------------------------
__global__ __launch_bounds__(128, 2)
void fused(const float* __restrict__ b1, const float* __restrict__ b2,
           float* __restrict__ out)
{
    extern __shared__ __half sh[];
    const int bid = blockIdx.x;
    const int tid = threadIdx.x;

    if (bid < G1N) {
        // ---- GEMM1: QKV projection ----
        int bm = bid / 24, bn = bid - bm * 24;
        gemm_body<1>(g_X, g_W1T, b1, (void*)g_QKV, bm, bn, H3, EDIM, sh);
        __threadfence();
        __syncthreads();
        if (tid == 0) atomicAdd(&g_cnt1[bm >> 4], 1);
    } else if (bid < G1N + ATN) {
        // ---- attention ----
        int idx = bid - G1N;
        int b = idx >> 8, rem = idx & 255;
        int qb = rem & 15, h = rem >> 4;
        if (tid == 0) {
            volatile int* c = &g_cnt1[b];
            while (*c < 384) { }
        }
        __syncthreads();
        __threadfence();
        attn_body(g_QKV + (size_t)b * SEQ * H3,
                  g_ATT + (size_t)b * SEQ * EDIM, qb, h, sh);
        __threadfence();
        __syncthreads();
        if (tid == 0) atomicAdd(&g_cnt2[b], 1);
    } else {
        // ---- GEMM2: output projection ----
        int idx = bid - (G1N + ATN);
        int bm = idx >> 3, bn = idx & 7;
        int b = bm >> 4;
        if (tid == 0) {
            volatile int* c = &g_cnt2[b];
            while (*c < 256) { }
        }
        __syncthreads();
        __threadfence();
        gemm_body<0>(g_ATT, g_W2T, b2, (void*)out, bm, bn, EDIM, EDIM, sh);
    }
}

// ---------------------------------------------------------------------------
extern "C" void kernel_launch(void* const* d_in, const int* in_sizes, int n_in,
                              void* d_out, int out_size)
{
    const float* x  = (const float*)d_in[0];
    const float* W1 = (const float*)d_in[1];
    const float* b1 = (const float*)d_in[2];
    const float* W2 = (const float*)d_in[3];
    const float* b2 = (const float*)d_in[4];
    float* out = (float*)d_out;

    const int fused_smem = 3 * 2 * 128 * 72 * 2;   // 110592 B (max of roles)
    static bool attr_done = false;
    if (!attr_done) {
        cudaFuncSetAttribute(fused,
                             cudaFuncAttributeMaxDynamicSharedMemorySize, fused_smem);
        attr_done = true;
    }

    // pre-pass: x -> half; W1 -> permuted W1T; W2 -> W2T; zero counters
    prepass<<<XB + W1B + W2B, 256>>>(x, W1, W2);

    // fused GEMM1 -> attention -> GEMM2 pipeline, one launch
    fused<<<G1N + ATN + G2N, 128, fused_smem>>>(b1, b2, out);
}